// round 2
// baseline (speedup 1.0000x reference)
#include <cuda_runtime.h>

// Problem constants
constexpr int CB   = 16;    // batch
constexpr int C    = 512;   // channels
constexpr int NPIX = 4096;  // H*W
constexpr int MQKV = 1536;  // 3*C

// Scratch (device globals — no allocation allowed)
__device__ float g_qkv[(size_t)CB * MQKV * NPIX];   // 402 MB
__device__ float g_attn[(size_t)CB * C * NPIX];     // 134 MB
__device__ float g_sc[CB * C];
__device__ float g_bi[CB * C];
__device__ float g_cconst[CB * MQKV];

// ---------------------------------------------------------------------------
// GroupNorm stats -> per (batch, channel) scale & bias
//   xn = sc*x + bi  with  sc = gamma*rstd,  bi = beta - mean*rstd*gamma
// ---------------------------------------------------------------------------
__global__ void gn_stats_kernel(const float* __restrict__ x,
                                const float* __restrict__ gamma,
                                const float* __restrict__ beta) {
    const int b = blockIdx.y, g = blockIdx.x;
    const int CPG = 16;                       // channels per group
    const float* xp = x + ((size_t)b * C + (size_t)g * CPG) * NPIX;

    float s = 0.f, s2 = 0.f;
    for (int i = threadIdx.x * 4; i < CPG * NPIX; i += blockDim.x * 4) {
        float4 v = *(const float4*)(xp + i);
        s  += v.x + v.y + v.z + v.w;
        s2 += v.x * v.x + v.y * v.y + v.z * v.z + v.w * v.w;
    }
    __shared__ float rs[32], rs2[32];
    for (int o = 16; o; o >>= 1) {
        s  += __shfl_down_sync(~0u, s,  o);
        s2 += __shfl_down_sync(~0u, s2, o);
    }
    int lane = threadIdx.x & 31, w = threadIdx.x >> 5;
    if (!lane) { rs[w] = s; rs2[w] = s2; }
    __syncthreads();
    if (threadIdx.x < 32) {
        int nw = blockDim.x >> 5;
        s  = (threadIdx.x < nw) ? rs[threadIdx.x]  : 0.f;
        s2 = (threadIdx.x < nw) ? rs2[threadIdx.x] : 0.f;
        for (int o = 16; o; o >>= 1) {
            s  += __shfl_down_sync(~0u, s,  o);
            s2 += __shfl_down_sync(~0u, s2, o);
        }
        if (!threadIdx.x) { rs[0] = s; rs2[0] = s2; }
    }
    __syncthreads();
    if (threadIdx.x < CPG) {
        const float inv  = 1.f / (float)(CPG * NPIX);
        float mean = rs[0] * inv;
        float var  = rs2[0] * inv - mean * mean;
        float rstd = rsqrtf(var + 1e-5f);
        int c = g * CPG + threadIdx.x;
        float ga = gamma[c];
        g_sc[b * C + c] = ga * rstd;
        g_bi[b * C + c] = beta[c] - mean * rstd * ga;
    }
}

// ---------------------------------------------------------------------------
// cconst[b][o] = b_qkv[o] + sum_c w_qkv[o][c] * bi[b][c]
// ---------------------------------------------------------------------------
__global__ void qkv_const_kernel(const float* __restrict__ w_qkv,
                                 const float* __restrict__ b_qkv) {
    int o = blockIdx.x * blockDim.x + threadIdx.x;   // 0..1535
    int b = blockIdx.y;
    const float* wr = w_qkv + (size_t)o * C;
    const float* bb = g_bi + b * C;
    float sum = b_qkv[o];
#pragma unroll 4
    for (int c = 0; c < C; c++) sum += wr[c] * bb[c];
    g_cconst[b * MQKV + o] = sum;
}

// ---------------------------------------------------------------------------
// Tiled SGEMM: out[b][M][N] = W[M,512] * Bmat[b][512][N] + epilogue
//   QKV=true : A' = W*diag(sc[b]),  B = x,      out = g_qkv, + cconst[b][row]
//   QKV=false: A  = w_proj,         B = g_attn, out = d_out, + b_proj + x
// BM=BN=128, BK=16, 256 threads, 8x8 per thread
// ---------------------------------------------------------------------------
template <bool QKV>
__global__ void __launch_bounds__(256, 2)
gemm_kernel(const float* __restrict__ W,
            const float* __restrict__ Xin,
            const float* __restrict__ bias,
            const float* __restrict__ resid,
            float* __restrict__ Out) {
    const int Mtot = QKV ? MQKV : C;
    const int b = blockIdx.z;
    const float* Bp = (QKV ? Xin : (const float*)g_attn)
                      + (size_t)b * C * NPIX + (size_t)blockIdx.x * 128;
    const float* Wp = W + (size_t)blockIdx.y * 128 * C;

    __shared__ float As[16][132];   // [k][m], padded
    __shared__ float Bs[16][128];   // [k][n]

    float acc[8][8];
#pragma unroll
    for (int i = 0; i < 8; i++)
#pragma unroll
        for (int j = 0; j < 8; j++) acc[i][j] = 0.f;

    const int tid = threadIdx.x;
    const int tr = tid >> 4;       // 0..15
    const int tc = tid & 15;       // 0..15
    const float* scp = g_sc + b * C;

    for (int k0 = 0; k0 < C; k0 += 16) {
#pragma unroll
        for (int i = 0; i < 2; i++) {
            int e = tid + i * 256;                 // 0..511
            // A tile: 128 rows x 16 k (float4 along k)
            int arow = e >> 2, akc = (e & 3) << 2;
            float4 va = *(const float4*)(Wp + (size_t)arow * C + k0 + akc);
            if (QKV) {
                va.x *= scp[k0 + akc + 0];
                va.y *= scp[k0 + akc + 1];
                va.z *= scp[k0 + akc + 2];
                va.w *= scp[k0 + akc + 3];
            }
            As[akc + 0][arow] = va.x;
            As[akc + 1][arow] = va.y;
            As[akc + 2][arow] = va.z;
            As[akc + 3][arow] = va.w;
            // B tile: 16 k x 128 n (float4 along n)
            int brow = e >> 5, bc = (e & 31) << 2;
            float4 vb = *(const float4*)(Bp + (size_t)(k0 + brow) * NPIX + bc);
            *(float4*)&Bs[brow][bc] = vb;
        }
        __syncthreads();
#pragma unroll
        for (int k = 0; k < 16; k++) {
            float a[8], bb[8];
            *(float4*)(a)      = *(const float4*)&As[k][tr * 4];
            *(float4*)(a + 4)  = *(const float4*)&As[k][64 + tr * 4];
            *(float4*)(bb)     = *(const float4*)&Bs[k][tc * 4];
            *(float4*)(bb + 4) = *(const float4*)&Bs[k][64 + tc * 4];
#pragma unroll
            for (int i = 0; i < 8; i++)
#pragma unroll
                for (int j = 0; j < 8; j++) acc[i][j] += a[i] * bb[j];
        }
        __syncthreads();
    }

    float* outp = QKV ? g_qkv : Out;
#pragma unroll
    for (int i = 0; i < 8; i++) {
        int rloc = (i < 4) ? (tr * 4 + i) : (64 + tr * 4 + i - 4);
        int row = blockIdx.y * 128 + rloc;
        float cadd = QKV ? g_cconst[b * MQKV + row] : bias[row];
        size_t obase = ((size_t)b * Mtot + row) * NPIX + (size_t)blockIdx.x * 128;
#pragma unroll
        for (int jh = 0; jh < 2; jh++) {
            int col = jh ? (64 + tc * 4) : (tc * 4);
            float4 o;
            o.x = acc[i][jh * 4 + 0] + cadd;
            o.y = acc[i][jh * 4 + 1] + cadd;
            o.z = acc[i][jh * 4 + 2] + cadd;
            o.w = acc[i][jh * 4 + 3] + cadd;
            if (!QKV) {
                float4 r = *(const float4*)(resid + obase + col);
                o.x += r.x; o.y += r.y; o.z += r.z; o.w += r.w;
            }
            *(float4*)(outp + obase + col) = o;
        }
    }
}

// ---------------------------------------------------------------------------
// Attention per (b, h): S[64,64] = Q K^T * scale; softmax over d; O = S V
// grid 128 blocks (b*8+h), 256 threads.
// smemA union: S-phase rows 0..31 = Q^T tile [n][c], rows 32..63 = K^T tile
//              [n][d]; O-phase = V tile [d][n] (64x64).
// ---------------------------------------------------------------------------
__global__ void __launch_bounds__(256) attn_kernel() {
    __shared__ float smemA[64][68];
    __shared__ float St[64][68];   // [d][c] = S^T, then softmaxed weights

    const int tid = threadIdx.x;
    const int bh = blockIdx.x;
    const int b = bh >> 3, h = bh & 7;
    const float* q    = g_qkv + ((size_t)b * MQKV + (size_t)h * 64) * NPIX;
    const float* kmat = q + (size_t)512 * NPIX;
    const float* vmat = q + (size_t)1024 * NPIX;
    float* op = g_attn + ((size_t)b * C + (size_t)h * 64) * NPIX;

    const int cb = (tid >> 4) << 2;   // 0..60 (c block)
    const int db = (tid & 15) << 2;   // 0..60 (d block / n block)
    const int w = tid >> 5, lane = tid & 31;

    float acc[4][4];
#pragma unroll
    for (int i = 0; i < 4; i++)
#pragma unroll
        for (int j = 0; j < 4; j++) acc[i][j] = 0.f;

    // ---- S = Q K^T  (accumulate over all N, 32-wide tiles) ----
    for (int n0 = 0; n0 < NPIX; n0 += 32) {
#pragma unroll
        for (int r = 0; r < 8; r++) {
            int row = w * 8 + r;                    // 0..63 (channel within head)
            smemA[lane][row]      = q   [(size_t)row * NPIX + n0 + lane];
            smemA[32 + lane][row] = kmat[(size_t)row * NPIX + n0 + lane];
        }
        __syncthreads();
#pragma unroll
        for (int n = 0; n < 32; n++) {
            float a0[4], b0[4];
            *(float4*)a0 = *(const float4*)&smemA[n][cb];        // Q^T
            *(float4*)b0 = *(const float4*)&smemA[32 + n][db];   // K^T
#pragma unroll
            for (int i = 0; i < 4; i++)
#pragma unroll
                for (int j = 0; j < 4; j++) acc[i][j] += a0[i] * b0[j];
        }
        __syncthreads();
    }

    // write S^T (scaled by d^-0.5 = 0.125)
#pragma unroll
    for (int i = 0; i < 4; i++)
#pragma unroll
        for (int j = 0; j < 4; j++)
            St[db + j][cb + i] = acc[i][j] * 0.125f;
    __syncthreads();

    // ---- softmax over d for each c ----
    if (tid < 64) {
        int c = tid;
        float mx = -1e30f;
        for (int d = 0; d < 64; d++) mx = fmaxf(mx, St[d][c]);
        float sum = 0.f;
        for (int d = 0; d < 64; d++) {
            float e = __expf(St[d][c] - mx);
            St[d][c] = e;
            sum += e;
        }
        float inv = 1.f / sum;
        for (int d = 0; d < 64; d++) St[d][c] *= inv;
    }
    __syncthreads();

    // ---- O = S V  (stream V over N, 64-wide tiles) ----
    for (int n0 = 0; n0 < NPIX; n0 += 64) {
#pragma unroll
        for (int i = 0; i < 4; i++) {
            int e = tid + i * 256;          // 0..1023
            int row = e >> 4;               // 0..63  (d)
            int col = (e & 15) << 2;        // 0..60  (n, float4)
            *(float4*)&smemA[row][col] =
                *(const float4*)(vmat + (size_t)row * NPIX + n0 + col);
        }
        __syncthreads();
        float o[4][4];
#pragma unroll
        for (int i = 0; i < 4; i++)
#pragma unroll
            for (int j = 0; j < 4; j++) o[i][j] = 0.f;
#pragma unroll
        for (int d = 0; d < 64; d++) {
            float a0[4], b0[4];
            *(float4*)a0 = *(const float4*)&St[d][cb];
            *(float4*)b0 = *(const float4*)&smemA[d][db];
#pragma unroll
            for (int i = 0; i < 4; i++)
#pragma unroll
                for (int j = 0; j < 4; j++) o[i][j] += a0[i] * b0[j];
        }
#pragma unroll
        for (int i = 0; i < 4; i++) {
            float4 vv = make_float4(o[i][0], o[i][1], o[i][2], o[i][3]);
            *(float4*)(op + (size_t)(cb + i) * NPIX + n0 + db) = vv;
        }
        __syncthreads();
    }
}

// ---------------------------------------------------------------------------
extern "C" void kernel_launch(void* const* d_in, const int* in_sizes, int n_in,
                              void* d_out, int out_size) {
    const float* x      = (const float*)d_in[0];
    const float* gamma  = (const float*)d_in[1];
    const float* beta   = (const float*)d_in[2];
    const float* w_qkv  = (const float*)d_in[3];
    const float* b_qkv  = (const float*)d_in[4];
    const float* w_proj = (const float*)d_in[5];
    const float* b_proj = (const float*)d_in[6];
    float* out = (float*)d_out;

    gn_stats_kernel<<<dim3(32, 16), 256>>>(x, gamma, beta);
    qkv_const_kernel<<<dim3(6, 16), 256>>>(w_qkv, b_qkv);
    gemm_kernel<true><<<dim3(32, 12, 16), 256>>>(w_qkv, x, nullptr, nullptr, nullptr);
    attn_kernel<<<128, 256>>>();
    gemm_kernel<false><<<dim3(32, 4, 16), 256>>>(w_proj, nullptr, b_proj, x, out);
}

// round 4
// speedup vs baseline: 1.2825x; 1.2825x over previous
#include <cuda_runtime.h>
#include <cuda_bf16.h>
#include <cstdint>

// Problem constants
constexpr int CB   = 16;
constexpr int C    = 512;
constexpr int NPIX = 4096;
constexpr int MQKV = 1536;

// Scratch (device globals)
__device__ float g_qkv[(size_t)CB * MQKV * NPIX];
__device__ float g_attn[(size_t)CB * C * NPIX];
__device__ float g_sc[CB * C];
__device__ float g_bi[CB * C];
__device__ __nv_bfloat16 g_xh[(size_t)CB * C * NPIX];
__device__ __nv_bfloat16 g_xl[(size_t)CB * C * NPIX];
__device__ __nv_bfloat16 g_wqh[MQKV * C], g_wql[MQKV * C];
__device__ __nv_bfloat16 g_wph[C * C],    g_wpl[C * C];

// ---------------- PTX helpers (base sm_103 ISA only) ----------------
__device__ __forceinline__ uint32_t smem_u32(const void* p) {
    uint32_t a;
    asm("{ .reg .u64 t; cvta.to.shared.u64 t, %1; cvt.u32.u64 %0, t; }" : "=r"(a) : "l"(p));
    return a;
}
__device__ __forceinline__ void cp_async16(uint32_t dst, const void* src) {
    asm volatile("cp.async.ca.shared.global [%0], [%1], 16;" :: "r"(dst), "l"(src));
}
#define CP_COMMIT() asm volatile("cp.async.commit_group;" ::: "memory")
#define CP_WAIT(n)  asm volatile("cp.async.wait_group %0;" :: "n"(n) : "memory")

__device__ __forceinline__ void ldsm_x4(uint32_t a, uint32_t& r0, uint32_t& r1,
                                        uint32_t& r2, uint32_t& r3) {
    asm volatile("ldmatrix.sync.aligned.m8n8.x4.shared.b16 {%0,%1,%2,%3}, [%4];"
                 : "=r"(r0), "=r"(r1), "=r"(r2), "=r"(r3) : "r"(a));
}
__device__ __forceinline__ void ldsm_x4t(uint32_t a, uint32_t& r0, uint32_t& r1,
                                         uint32_t& r2, uint32_t& r3) {
    asm volatile("ldmatrix.sync.aligned.m8n8.x4.trans.shared.b16 {%0,%1,%2,%3}, [%4];"
                 : "=r"(r0), "=r"(r1), "=r"(r2), "=r"(r3) : "r"(a));
}
__device__ __forceinline__ void mma16816(float* c, const uint32_t* a, const uint32_t* b) {
    asm volatile("mma.sync.aligned.m16n8k16.row.col.f32.bf16.bf16.f32 "
                 "{%0,%1,%2,%3}, {%4,%5,%6,%7}, {%8,%9}, {%0,%1,%2,%3};"
                 : "+f"(c[0]), "+f"(c[1]), "+f"(c[2]), "+f"(c[3])
                 : "r"(a[0]), "r"(a[1]), "r"(a[2]), "r"(a[3]), "r"(b[0]), "r"(b[1]));
}

// ---------------------------------------------------------------------------
// GroupNorm stats -> per (b,c) scale & bias
// ---------------------------------------------------------------------------
__global__ void gn_stats_kernel(const float* __restrict__ x,
                                const float* __restrict__ gamma,
                                const float* __restrict__ beta) {
    const int b = blockIdx.y, g = blockIdx.x;
    const int CPG = 16;
    const float* xp = x + ((size_t)b * C + (size_t)g * CPG) * NPIX;

    float s = 0.f, s2 = 0.f;
    for (int i = threadIdx.x * 4; i < CPG * NPIX; i += blockDim.x * 4) {
        float4 v = *(const float4*)(xp + i);
        s  += v.x + v.y + v.z + v.w;
        s2 += v.x * v.x + v.y * v.y + v.z * v.z + v.w * v.w;
    }
    __shared__ float rs[32], rs2[32];
    for (int o = 16; o; o >>= 1) {
        s  += __shfl_down_sync(~0u, s,  o);
        s2 += __shfl_down_sync(~0u, s2, o);
    }
    int lane = threadIdx.x & 31, w = threadIdx.x >> 5;
    if (!lane) { rs[w] = s; rs2[w] = s2; }
    __syncthreads();
    if (threadIdx.x < 32) {
        int nw = blockDim.x >> 5;
        s  = (threadIdx.x < nw) ? rs[threadIdx.x]  : 0.f;
        s2 = (threadIdx.x < nw) ? rs2[threadIdx.x] : 0.f;
        for (int o = 16; o; o >>= 1) {
            s  += __shfl_down_sync(~0u, s,  o);
            s2 += __shfl_down_sync(~0u, s2, o);
        }
        if (!threadIdx.x) { rs[0] = s; rs2[0] = s2; }
    }
    __syncthreads();
    if (threadIdx.x < CPG) {
        const float inv = 1.f / (float)(CPG * NPIX);
        float mean = rs[0] * inv;
        float var  = rs2[0] * inv - mean * mean;
        float rstd = rsqrtf(var + 1e-5f);
        int c = g * CPG + threadIdx.x;
        float ga = gamma[c];
        g_sc[b * C + c] = ga * rstd;
        g_bi[b * C + c] = beta[c] - mean * rstd * ga;
    }
}

// ---------------------------------------------------------------------------
// fp32 -> bf16 hi/lo split
// ---------------------------------------------------------------------------
__device__ __forceinline__ void splt(float v, unsigned short& h, unsigned short& l) {
    __nv_bfloat16 hb = __float2bfloat16(v);
    __nv_bfloat16 lb = __float2bfloat16(v - __bfloat162float(hb));
    h = __bfloat16_as_ushort(hb);
    l = __bfloat16_as_ushort(lb);
}

// MODE 0: src = x, apply GroupNorm affine. MODE 1: src = g_attn, identity.
template <int MODE>
__global__ void convert_split(const float* __restrict__ srcp) {
    size_t i = ((size_t)blockIdx.x * 256 + threadIdx.x) * 4;
    const float* src = (MODE == 0) ? srcp : (const float*)g_attn;
    float4 v = *(const float4*)(src + i);
    if (MODE == 0) {
        int bc = (int)(i >> 12);
        float s = g_sc[bc], o = g_bi[bc];
        v.x = fmaf(v.x, s, o); v.y = fmaf(v.y, s, o);
        v.z = fmaf(v.z, s, o); v.w = fmaf(v.w, s, o);
    }
    ushort4 hh, ll;
    splt(v.x, hh.x, ll.x); splt(v.y, hh.y, ll.y);
    splt(v.z, hh.z, ll.z); splt(v.w, hh.w, ll.w);
    *(ushort4*)(g_xh + i) = hh;
    *(ushort4*)(g_xl + i) = ll;
}

__global__ void convert_w(const float* __restrict__ src, int which) {
    size_t i = ((size_t)blockIdx.x * 256 + threadIdx.x) * 4;
    float4 v = *(const float4*)(src + i);
    __nv_bfloat16* dh = which ? g_wph : g_wqh;
    __nv_bfloat16* dl = which ? g_wpl : g_wql;
    ushort4 hh, ll;
    splt(v.x, hh.x, ll.x); splt(v.y, hh.y, ll.y);
    splt(v.z, hh.z, ll.z); splt(v.w, hh.w, ll.w);
    *(ushort4*)(dh + i) = hh;
    *(ushort4*)(dl + i) = ll;
}

// ---------------------------------------------------------------------------
// HMMA (mma.sync bf16) GEMM with 3-term hi/lo split.
// Out[b][M][N] = W @ Xn (+bias, +residual)
// CTA: 128(M) x 128(N). 8 warps, each 64x32. K=512 in 32 chunks of 16.
// 2-stage cp.async pipeline.
// Stage layout (bytes):
//   A (term t): off = t*6144,       row m (0..127), stride 48, k-seg*16
//   B (term t): off = 12288+t*4352, row k (0..15),  stride 272, n*2
// ---------------------------------------------------------------------------
constexpr int STAGE = 20992;   // 2*6144 + 2*4352
constexpr int B_OFF = 12288;

template <bool QKV>
__global__ void __launch_bounds__(256)
gemm_mma(const float* __restrict__ bias, const float* __restrict__ resid,
         float* __restrict__ OutP) {
    __shared__ __align__(16) char smem[2 * STAGE];
    const uint32_t sb = smem_u32(smem);

    const int tid = threadIdx.x, lane = tid & 31, wid = tid >> 5;
    const int nb = blockIdx.x, mb = blockIdx.y, b = blockIdx.z;
    const int Mtot = QKV ? MQKV : C;
    const int wm = wid >> 2, wn = wid & 3;           // warp tile: (wm*64, wn*32)

    const __nv_bfloat16* wsrc[2] = {
        (QKV ? g_wqh : g_wph) + (size_t)mb * 128 * 512,
        (QKV ? g_wql : g_wpl) + (size_t)mb * 128 * 512 };
    const __nv_bfloat16* xsrc[2] = {
        g_xh + (size_t)b * C * NPIX,
        g_xl + (size_t)b * C * NPIX };

    // per-thread load slots (computed once)
    const int a_term = tid >> 7, a_g = tid & 127;     // handled twice per stage
    // stage loader: 2 A-iters (512 granules) + 2 B-iters (512 granules)
    auto load_stage = [&](int ch, int st) {
        uint32_t sbase = sb + st * STAGE;
#pragma unroll
        for (int it = 0; it < 2; it++) {
            int idx = tid + it * 256;                 // 0..511
            int t = idx >> 8, g = idx & 255;
            int m = g >> 1, seg = g & 1;
            cp_async16(sbase + t * 6144 + m * 48 + seg * 16,
                       wsrc[t] + (size_t)m * 512 + ch * 16 + seg * 8);
        }
#pragma unroll
        for (int it = 0; it < 2; it++) {
            int idx = tid + it * 256;
            int t = idx >> 8, g = idx & 255;
            int row = g >> 4, seg = g & 15;
            cp_async16(sbase + B_OFF + t * 4352 + row * 272 + seg * 16,
                       xsrc[t] + (size_t)(ch * 16 + row) * NPIX + nb * 128 + seg * 8);
        }
        CP_COMMIT();
    };

    float acc[4][4][4];
#pragma unroll
    for (int i = 0; i < 4; i++)
#pragma unroll
        for (int j = 0; j < 4; j++)
#pragma unroll
            for (int r = 0; r < 4; r++) acc[i][j][r] = 0.f;

    const uint32_t arow = lane & 15, aseg = lane >> 4;
    const uint32_t brow = lane & 15, bseg = lane >> 4;

    load_stage(0, 0);

    for (int ch = 0; ch < 32; ch++) {
        const int st = ch & 1;
        if (ch + 1 < 32) { load_stage(ch + 1, st ^ 1); CP_WAIT(1); }
        else             { CP_WAIT(0); }
        __syncthreads();

        const uint32_t sbase = sb + st * STAGE;
        uint32_t ah[4][4], al[4][4], bh[4][2], bl[4][2];
#pragma unroll
        for (int i = 0; i < 4; i++) {
            uint32_t ra = sbase + (wm * 64 + i * 16 + arow) * 48 + aseg * 16;
            ldsm_x4(ra,        ah[i][0], ah[i][1], ah[i][2], ah[i][3]);
            ldsm_x4(ra + 6144, al[i][0], al[i][1], al[i][2], al[i][3]);
        }
#pragma unroll
        for (int j2 = 0; j2 < 2; j2++) {
            uint32_t rb = sbase + B_OFF + brow * 272 + (wn * 32 + j2 * 16 + bseg * 8) * 2;
            ldsm_x4t(rb,        bh[j2*2][0], bh[j2*2][1], bh[j2*2+1][0], bh[j2*2+1][1]);
            ldsm_x4t(rb + 4352, bl[j2*2][0], bl[j2*2][1], bl[j2*2+1][0], bl[j2*2+1][1]);
        }
#pragma unroll
        for (int i = 0; i < 4; i++)
#pragma unroll
            for (int j = 0; j < 4; j++) {
                mma16816(acc[i][j], ah[i], bh[j]);
                mma16816(acc[i][j], ah[i], bl[j]);
                mma16816(acc[i][j], al[i], bh[j]);
            }
        __syncthreads();
    }

    // Epilogue
    float* outp = QKV ? g_qkv : OutP;
    const int gid = lane >> 2, tig = lane & 3;
#pragma unroll
    for (int i = 0; i < 4; i++) {
        int r0 = mb * 128 + wm * 64 + i * 16 + gid;
        int r1 = r0 + 8;
        float bz0 = bias[r0], bz1 = bias[r1];
        size_t o0 = ((size_t)b * Mtot + r0) * NPIX + nb * 128 + wn * 32 + 2 * tig;
        size_t o1 = ((size_t)b * Mtot + r1) * NPIX + nb * 128 + wn * 32 + 2 * tig;
#pragma unroll
        for (int j = 0; j < 4; j++) {
            float2 v0 = make_float2(acc[i][j][0] + bz0, acc[i][j][1] + bz0);
            float2 v1 = make_float2(acc[i][j][2] + bz1, acc[i][j][3] + bz1);
            if (!QKV) {
                float2 q0 = *(const float2*)(resid + o0 + j * 8);
                float2 q1 = *(const float2*)(resid + o1 + j * 8);
                v0.x += q0.x; v0.y += q0.y;
                v1.x += q1.x; v1.y += q1.y;
            }
            *(float2*)(outp + o0 + j * 8) = v0;
            *(float2*)(outp + o1 + j * 8) = v1;
        }
    }
}

// ---------------------------------------------------------------------------
// Attention per (b, h) — unchanged (correct, ~394us)
// ---------------------------------------------------------------------------
__global__ void __launch_bounds__(256) attn_kernel() {
    __shared__ float smemA[64][68];
    __shared__ float St[64][68];

    const int tid = threadIdx.x;
    const int bh = blockIdx.x;
    const int b = bh >> 3, h = bh & 7;
    const float* q    = g_qkv + ((size_t)b * MQKV + (size_t)h * 64) * NPIX;
    const float* kmat = q + (size_t)512 * NPIX;
    const float* vmat = q + (size_t)1024 * NPIX;
    float* op = g_attn + ((size_t)b * C + (size_t)h * 64) * NPIX;

    const int cb = (tid >> 4) << 2;
    const int db = (tid & 15) << 2;
    const int w = tid >> 5, lane = tid & 31;

    float acc[4][4];
#pragma unroll
    for (int i = 0; i < 4; i++)
#pragma unroll
        for (int j = 0; j < 4; j++) acc[i][j] = 0.f;

    for (int n0 = 0; n0 < NPIX; n0 += 32) {
#pragma unroll
        for (int r = 0; r < 8; r++) {
            int row = w * 8 + r;
            smemA[lane][row]      = q   [(size_t)row * NPIX + n0 + lane];
            smemA[32 + lane][row] = kmat[(size_t)row * NPIX + n0 + lane];
        }
        __syncthreads();
#pragma unroll
        for (int n = 0; n < 32; n++) {
            float a0[4], b0[4];
            *(float4*)a0 = *(const float4*)&smemA[n][cb];
            *(float4*)b0 = *(const float4*)&smemA[32 + n][db];
#pragma unroll
            for (int i = 0; i < 4; i++)
#pragma unroll
                for (int j = 0; j < 4; j++) acc[i][j] += a0[i] * b0[j];
        }
        __syncthreads();
    }

#pragma unroll
    for (int i = 0; i < 4; i++)
#pragma unroll
        for (int j = 0; j < 4; j++)
            St[db + j][cb + i] = acc[i][j] * 0.125f;
    __syncthreads();

    if (tid < 64) {
        int c = tid;
        float mx = -1e30f;
        for (int d = 0; d < 64; d++) mx = fmaxf(mx, St[d][c]);
        float sum = 0.f;
        for (int d = 0; d < 64; d++) {
            float e = __expf(St[d][c] - mx);
            St[d][c] = e;
            sum += e;
        }
        float inv = 1.f / sum;
        for (int d = 0; d < 64; d++) St[d][c] *= inv;
    }
    __syncthreads();

    for (int n0 = 0; n0 < NPIX; n0 += 64) {
#pragma unroll
        for (int i = 0; i < 4; i++) {
            int e = tid + i * 256;
            int row = e >> 4;
            int col = (e & 15) << 2;
            *(float4*)&smemA[row][col] =
                *(const float4*)(vmat + (size_t)row * NPIX + n0 + col);
        }
        __syncthreads();
        float o[4][4];
#pragma unroll
        for (int i = 0; i < 4; i++)
#pragma unroll
            for (int j = 0; j < 4; j++) o[i][j] = 0.f;
#pragma unroll
        for (int d = 0; d < 64; d++) {
            float a0[4], b0[4];
            *(float4*)a0 = *(const float4*)&St[d][cb];
            *(float4*)b0 = *(const float4*)&smemA[d][db];
#pragma unroll
            for (int i = 0; i < 4; i++)
#pragma unroll
                for (int j = 0; j < 4; j++) o[i][j] += a0[i] * b0[j];
        }
#pragma unroll
        for (int i = 0; i < 4; i++) {
            float4 vv = make_float4(o[i][0], o[i][1], o[i][2], o[i][3]);
            *(float4*)(op + (size_t)(cb + i) * NPIX + n0 + db) = vv;
        }
        __syncthreads();
    }
}

// ---------------------------------------------------------------------------
extern "C" void kernel_launch(void* const* d_in, const int* in_sizes, int n_in,
                              void* d_out, int out_size) {
    const float* x      = (const float*)d_in[0];
    const float* gamma  = (const float*)d_in[1];
    const float* beta   = (const float*)d_in[2];
    const float* w_qkv  = (const float*)d_in[3];
    const float* b_qkv  = (const float*)d_in[4];
    const float* w_proj = (const float*)d_in[5];
    const float* b_proj = (const float*)d_in[6];
    float* out = (float*)d_out;

    gn_stats_kernel<<<dim3(32, 16), 256>>>(x, gamma, beta);
    convert_w<<<768, 256>>>(w_qkv, 0);
    convert_w<<<256, 256>>>(w_proj, 1);
    convert_split<0><<<32768, 256>>>(x);
    gemm_mma<true><<<dim3(32, 12, 16), 256>>>(b_qkv, nullptr, nullptr);
    attn_kernel<<<128, 256>>>();
    convert_split<1><<<32768, 256>>>(x);
    gemm_mma<false><<<dim3(32, 4, 16), 256>>>(b_proj, x, out);
}